// round 4
// baseline (speedup 1.0000x reference)
#include <cuda_runtime.h>

typedef unsigned long long ull;

__device__ __forceinline__ ull pack2(float lo, float hi) {
    ull r; asm("mov.b64 %0, {%1, %2};" : "=l"(r) : "f"(lo), "f"(hi)); return r;
}
__device__ __forceinline__ void unpack2(ull v, float& lo, float& hi) {
    asm("mov.b64 {%0, %1}, %2;" : "=f"(lo), "=f"(hi) : "l"(v));
}
__device__ __forceinline__ void ffma2(ull& d, ull a, ull b) {
    asm("fma.rn.f32x2 %0, %1, %2, %0;" : "+l"(d) : "l"(a), "l"(b));
}

// ---------------- scratch (device globals; no allocations allowed) ----------
__device__ float g_t1 [8 * 32 * 128 * 128];      // project1 conv1 out (ReLU)
__device__ float g_g  [8 * 32 * 128 * 128];      // guidance conv1 out (ReLU)
__device__ float g_xp [8 * 16 * 128 * 128];      // project1 conv2 out (ReLU)
__device__ float g_wts[8 * 16 * 9 * 128 * 128];  // softmax weights (n, pq, k, hw)
__device__ float g_up [8 * 16 * 512 * 512];      // upsampled NCHW
__device__ float g_mid[8 *  8 * 512 * 512];      // project2 conv1 out (ReLU)

// --------- direct conv, f32x2 channel-pair accumulators, PX pixels/thread ---
// block = 16x16 threads; tile = (PX*16) x 16 outputs; CB out-channels/block.
template <int CIN, int COUT, int CB, int K, int PX, bool RELU>
__global__ __launch_bounds__(256, 2)
void conv2d_kernel(const float* __restrict__ in,
                   const float* __restrict__ wgt,
                   const float* __restrict__ bias,
                   float* __restrict__ out,
                   int H, int W)
{
    constexpr int TX = 16, TY = 16;
    constexpr int TW = TX * PX;
    constexpr int SX = TW + K - 1;
    constexpr int SY = TY + K - 1;
    // pad row stride so the two half-warps of a row-pair land on disjoint banks
    constexpr int SP = ((SX + 15) / 32) * 32 + 16;   // ≡16 (mod 32), >= SX
    constexpr int PAD = K / 2;
    constexpr int KK = K * K;
    constexpr int NGRP = COUT / CB;
    constexpr int CB2 = CB / 2;

    __shared__ __align__(16) float s_in[SY * SP];
    __shared__ __align__(16) float s_w[KK * CB];

    const int n   = blockIdx.z / NGRP;
    const int grp = blockIdx.z % NGRP;
    const int h0  = blockIdx.y * TY;
    const int w0  = blockIdx.x * TW;
    const int tx  = threadIdx.x, ty = threadIdx.y;
    const int tid = ty * TX + tx;

    ull acc[PX][CB2];
#pragma unroll
    for (int j = 0; j < CB2; j++) {
        ull b = pack2(bias[grp * CB + 2 * j], bias[grp * CB + 2 * j + 1]);
#pragma unroll
        for (int px = 0; px < PX; px++) acc[px][j] = b;
    }

    for (int cin = 0; cin < CIN; cin++) {
        __syncthreads();
        // input tile (zero-padded)
        for (int i = tid; i < SY * SX; i += 256) {
            int r = i / SX, c = i % SX;
            int gh = h0 + r - PAD, gw = w0 + c - PAD;
            float v = 0.f;
            if (gh >= 0 && gh < H && gw >= 0 && gw < W)
                v = in[((n * CIN + cin) * H + gh) * W + gw];
            s_in[r * SP + c] = v;
        }
        // weight slice for this cin -> [k][co]
        for (int i = tid; i < KK * CB; i += 256) {
            int co = i % CB, kidx = i / CB;
            s_w[i] = wgt[((grp * CB + co) * CIN + cin) * KK + kidx];
        }
        __syncthreads();

#pragma unroll
        for (int kh = 0; kh < K; kh++) {
#pragma unroll
            for (int kw = 0; kw < K; kw++) {
                const ull* wp = (const ull*)&s_w[(kh * K + kw) * CB];
                ull vv[PX];
#pragma unroll
                for (int px = 0; px < PX; px++) {
                    float v = s_in[(ty + kh) * SP + tx + px * TX + kw];
                    vv[px] = pack2(v, v);
                }
#pragma unroll
                for (int j = 0; j < CB2; j++) {
                    ull w2 = wp[j];     // warp-uniform LDS.64 broadcast
#pragma unroll
                    for (int px = 0; px < PX; px++)
                        ffma2(acc[px][j], vv[px], w2);
                }
            }
        }
    }

    const int h = h0 + ty;
#pragma unroll
    for (int j = 0; j < CB2; j++) {
#pragma unroll
        for (int px = 0; px < PX; px++) {
            float lo, hi;
            unpack2(acc[px][j], lo, hi);
            if (RELU) { lo = fmaxf(lo, 0.f); hi = fmaxf(hi, 0.f); }
            const int w = w0 + px * TX + tx;
            out[((n * COUT + grp * CB + 2 * j)     * H + h) * W + w] = lo;
            out[((n * COUT + grp * CB + 2 * j + 1) * H + h) * W + w] = hi;
        }
    }
}

// ------------- guidance 1x1 conv (32->144) + per-(p,q) softmax over 9 -------
// wts layout: [((n*16 + pq)*9 + k) * HW + hw]
__global__ void gw_softmax_kernel(const float* __restrict__ g,
                                  const float* __restrict__ w2,
                                  const float* __restrict__ b2,
                                  float* __restrict__ wts)
{
    constexpr int HW = 128 * 128;
    __shared__ __align__(16) float s_w[144 * 32];
    __shared__ float s_b[144];
    for (int i = threadIdx.x; i < 144 * 32; i += 256) s_w[i] = w2[i];
    for (int i = threadIdx.x; i < 144;      i += 256) s_b[i] = b2[i];
    __syncthreads();

    const int pix = blockIdx.x * 256 + threadIdx.x;   // exactly 8*16384
    const int n = pix / HW, hw = pix % HW;

    ull gv[16];
#pragma unroll
    for (int j = 0; j < 16; j++) {
        float a = g[(n * 32 + 2 * j)     * HW + hw];
        float b = g[(n * 32 + 2 * j + 1) * HW + hw];
        gv[j] = pack2(a, b);
    }

    for (int pq = 0; pq < 16; pq++) {
        float v[9];
#pragma unroll
        for (int k = 0; k < 9; k++) {
            const int ch = k * 16 + pq;          // channel order: k*16 + p*4 + q
            const ull* wp = (const ull*)&s_w[ch * 32];
            ull a2 = pack2(0.f, 0.f);
#pragma unroll
            for (int j = 0; j < 16; j++) ffma2(a2, gv[j], wp[j]);
            float lo, hi; unpack2(a2, lo, hi);
            v[k] = s_b[ch] + lo + hi;
        }
        float m = v[0];
#pragma unroll
        for (int k = 1; k < 9; k++) m = fmaxf(m, v[k]);
        float s = 0.f;
#pragma unroll
        for (int k = 0; k < 9; k++) { v[k] = __expf(v[k] - m); s += v[k]; }
        const float inv = 1.f / s;
#pragma unroll
        for (int k = 0; k < 9; k++)
            wts[((n * 16 + pq) * 9 + k) * HW + hw] = v[k] * inv;
    }
}

// ------------- convex upsample + pixel shuffle ------------------------------
__global__ void upsample_kernel(const float* __restrict__ xp,
                                const float* __restrict__ wts,
                                float* __restrict__ up)
{
    constexpr int H = 128, W = 128, HW = H * W;
    __shared__ float s_xp[16][3][18];

    const int n = blockIdx.z, h = blockIdx.y, wtile = blockIdx.x * 16;
    const int tid = threadIdx.y * 64 + threadIdx.x;

    for (int i = tid; i < 16 * 3 * 18; i += 256) {
        int c = i / 54, rem = i % 54, r = rem / 18, col = rem % 18;
        int gh = h + r - 1, gw = wtile + col - 1;
        float v = 0.f;
        if (gh >= 0 && gh < H && gw >= 0 && gw < W)
            v = xp[(n * 16 + c) * HW + gh * W + gw];
        s_xp[c][r][col] = v;
    }
    __syncthreads();

    const int p  = threadIdx.y;
    const int q  = threadIdx.x & 3;
    const int wl = threadIdx.x >> 2;
    const int pq = p * 4 + q;
    const int hw = h * W + wtile + wl;

    float wt[9];
#pragma unroll
    for (int k = 0; k < 9; k++) wt[k] = wts[((n * 16 + pq) * 9 + k) * HW + hw];

    const int h_hi = h * 4 + p;
    const int w_hi = (wtile + wl) * 4 + q;
#pragma unroll
    for (int c = 0; c < 16; c++) {
        float acc = 0.f;
#pragma unroll
        for (int i = 0; i < 3; i++)
#pragma unroll
            for (int j = 0; j < 3; j++)
                acc = fmaf(wt[i * 3 + j], s_xp[c][i][wl + j], acc);
        up[((n * 16 + c) * 512 + h_hi) * 512 + w_hi] = acc;
    }
}

// ---------------------------------------------------------------------------
extern "C" void kernel_launch(void* const* d_in, const int* in_sizes, int n_in,
                              void* d_out, int out_size)
{
    const float* x     = (const float*)d_in[0];
    const float* p1_w1 = (const float*)d_in[1];
    const float* p1_b1 = (const float*)d_in[2];
    const float* p1_w2 = (const float*)d_in[3];
    const float* p1_b2 = (const float*)d_in[4];
    const float* gw_w1 = (const float*)d_in[5];
    const float* gw_b1 = (const float*)d_in[6];
    const float* gw_w2 = (const float*)d_in[7];
    const float* gw_b2 = (const float*)d_in[8];
    const float* p2_w1 = (const float*)d_in[9];
    const float* p2_b1 = (const float*)d_in[10];
    const float* p2_w2 = (const float*)d_in[11];
    const float* p2_b2 = (const float*)d_in[12];
    float* out = (float*)d_out;

    float *t1, *gg, *xp, *wts, *up, *mid;
    cudaGetSymbolAddress((void**)&t1,  g_t1);
    cudaGetSymbolAddress((void**)&gg,  g_g);
    cudaGetSymbolAddress((void**)&xp,  g_xp);
    cudaGetSymbolAddress((void**)&wts, g_wts);
    cudaGetSymbolAddress((void**)&up,  g_up);
    cudaGetSymbolAddress((void**)&mid, g_mid);

    dim3 b16(16, 16);

    // project1 conv1 (64->32, k3, ReLU): tile 32x16, CB=16 (2 groups)
    conv2d_kernel<64, 32, 16, 3, 2, true><<<dim3(4, 8, 16), b16>>>(x, p1_w1, p1_b1, t1, 128, 128);
    // guidance conv1 (64->32, k3, ReLU)
    conv2d_kernel<64, 32, 16, 3, 2, true><<<dim3(4, 8, 16), b16>>>(x, gw_w1, gw_b1, gg, 128, 128);
    // project1 conv2 (32->16, k3, ReLU)
    conv2d_kernel<32, 16, 16, 3, 2, true><<<dim3(4, 8, 8), b16>>>(t1, p1_w2, p1_b2, xp, 128, 128);
    // guidance 1x1 (32->144) + group softmax
    gw_softmax_kernel<<<512, 256>>>(gg, gw_w2, gw_b2, wts);
    // convex upsample + pixel shuffle -> (8,16,512,512)
    upsample_kernel<<<dim3(8, 128, 8), dim3(64, 4)>>>(xp, wts, up);
    // project2 conv1 (16->8, k5, ReLU) @512x512: tile 64x16, PX=4, CB=8
    conv2d_kernel<16, 8, 8, 5, 4, true><<<dim3(8, 32, 8), b16>>>(up, p2_w1, p2_b1, mid, 512, 512);
    // project2 conv2 (8->64, k3) @512x512: tile 32x16, CB=16 (4 groups)
    conv2d_kernel<8, 64, 16, 3, 2, false><<<dim3(16, 32, 32), b16>>>(mid, p2_w2, p2_b2, out, 512, 512);
}

// round 5
// speedup vs baseline: 1.0401x; 1.0401x over previous
#include <cuda_runtime.h>

// ---------------- scratch (device globals; no allocations allowed) ----------
__device__ float g_t1 [8 * 32 * 128 * 128];      // project1 conv1 out (ReLU)
__device__ float g_g  [8 * 32 * 128 * 128];      // guidance conv1 out (ReLU)
__device__ float g_xp [8 * 16 * 128 * 128];      // project1 conv2 out (ReLU)
__device__ float g_wts[8 * 16 * 9 * 128 * 128];  // softmax weights (n, pq, k, hw)
__device__ float g_up [8 * 16 * 512 * 512];      // upsampled NCHW
__device__ float g_mid[8 *  8 * 512 * 512];      // project2 conv1 out (ReLU)

// --------- direct conv: PX pixels/thread, CB channels/block, reg-cached w ---
// block = 16x16 threads; tile = (PX*16) wide x 16 tall outputs.
// Inner loop per tap: CB/4 x LDS.128 (weights, broadcast) + PX x LDS (input)
// + CB*PX FFMA  ->  FFMA-pipe bound.
template <int CIN, int COUT, int CB, int K, int PX, bool RELU>
__global__ __launch_bounds__(256, 2)
void conv2d_kernel(const float* __restrict__ in,
                   const float* __restrict__ wgt,
                   const float* __restrict__ bias,
                   float* __restrict__ out,
                   int H, int W)
{
    constexpr int TX = 16, TY = 16;
    constexpr int TW = TX * PX;
    constexpr int SX = TW + K - 1;
    constexpr int SY = TY + K - 1;
    // row stride ≡ 16 (mod 32): the two half-warp rows hit disjoint banks
    constexpr int SP = ((SX + 15) / 32) * 32 + 16;
    constexpr int PAD = K / 2;
    constexpr int KK = K * K;
    constexpr int NGRP = COUT / CB;

    __shared__ __align__(16) float s_in[SY * SP];
    __shared__ __align__(16) float s_w[KK * CB];

    const int n   = blockIdx.z / NGRP;
    const int grp = blockIdx.z % NGRP;
    const int h0  = blockIdx.y * TY;
    const int w0  = blockIdx.x * TW;
    const int tx  = threadIdx.x, ty = threadIdx.y;
    const int tid = ty * TX + tx;

    float acc[PX][CB];
#pragma unroll
    for (int j = 0; j < CB; j++) {
        float b = bias[grp * CB + j];
#pragma unroll
        for (int px = 0; px < PX; px++) acc[px][j] = b;
    }

    for (int cin = 0; cin < CIN; cin++) {
        __syncthreads();
        // input tile (zero-padded)
        for (int i = tid; i < SY * SX; i += 256) {
            int r = i / SX, c = i % SX;
            int gh = h0 + r - PAD, gw = w0 + c - PAD;
            float v = 0.f;
            if (gh >= 0 && gh < H && gw >= 0 && gw < W)
                v = in[((n * CIN + cin) * H + gh) * W + gw];
            s_in[r * SP + c] = v;
        }
        // weight slice for this cin -> [k][co] contiguous
        for (int i = tid; i < KK * CB; i += 256) {
            int co = i % CB, kidx = i / CB;
            s_w[i] = wgt[((grp * CB + co) * CIN + cin) * KK + kidx];
        }
        __syncthreads();

#pragma unroll
        for (int kh = 0; kh < K; kh++) {
            const float* row = &s_in[(ty + kh) * SP + tx];
#pragma unroll
            for (int kw = 0; kw < K; kw++) {
                const float4* wp = (const float4*)&s_w[(kh * K + kw) * CB];
                float w[CB];
#pragma unroll
                for (int j4 = 0; j4 < CB / 4; j4++) {
                    float4 t = wp[j4];           // LDS.128, warp-uniform
                    w[4 * j4 + 0] = t.x; w[4 * j4 + 1] = t.y;
                    w[4 * j4 + 2] = t.z; w[4 * j4 + 3] = t.w;
                }
                float v[PX];
#pragma unroll
                for (int px = 0; px < PX; px++)
                    v[px] = row[px * TX + kw];
#pragma unroll
                for (int j = 0; j < CB; j++)
#pragma unroll
                    for (int px = 0; px < PX; px++)
                        acc[px][j] = fmaf(v[px], w[j], acc[px][j]);
            }
        }
    }

    const int h = h0 + ty;
#pragma unroll
    for (int j = 0; j < CB; j++) {
#pragma unroll
        for (int px = 0; px < PX; px++) {
            float v = acc[px][j];
            if (RELU) v = fmaxf(v, 0.f);
            out[((n * COUT + grp * CB + j) * H + h) * W + (w0 + px * TX + tx)] = v;
        }
    }
}

// ------------- guidance 1x1 conv (32->144) + per-(p,q) softmax over 9 -------
// wts layout: [((n*16 + pq)*9 + k) * HW + hw]
__global__ void gw_softmax_kernel(const float* __restrict__ g,
                                  const float* __restrict__ w2,
                                  const float* __restrict__ b2,
                                  float* __restrict__ wts)
{
    constexpr int HW = 128 * 128;
    __shared__ __align__(16) float s_w[144 * 32];
    __shared__ float s_b[144];
    for (int i = threadIdx.x; i < 144 * 32; i += 256) s_w[i] = w2[i];
    for (int i = threadIdx.x; i < 144;      i += 256) s_b[i] = b2[i];
    __syncthreads();

    const int pix = blockIdx.x * 256 + threadIdx.x;   // exactly 8*16384
    const int n = pix / HW, hw = pix % HW;

    float gv[32];
#pragma unroll
    for (int c = 0; c < 32; c++) gv[c] = g[(n * 32 + c) * HW + hw];

    for (int pq = 0; pq < 16; pq++) {
        float v[9];
#pragma unroll
        for (int k = 0; k < 9; k++) {
            const int ch = k * 16 + pq;          // channel order: k*16 + p*4 + q
            const float4* wp = (const float4*)&s_w[ch * 32];
            float acc = s_b[ch];
#pragma unroll
            for (int j4 = 0; j4 < 8; j4++) {
                float4 t = wp[j4];               // LDS.128 broadcast
                acc = fmaf(gv[4 * j4 + 0], t.x, acc);
                acc = fmaf(gv[4 * j4 + 1], t.y, acc);
                acc = fmaf(gv[4 * j4 + 2], t.z, acc);
                acc = fmaf(gv[4 * j4 + 3], t.w, acc);
            }
            v[k] = acc;
        }
        float m = v[0];
#pragma unroll
        for (int k = 1; k < 9; k++) m = fmaxf(m, v[k]);
        float s = 0.f;
#pragma unroll
        for (int k = 0; k < 9; k++) { v[k] = __expf(v[k] - m); s += v[k]; }
        const float inv = 1.f / s;
#pragma unroll
        for (int k = 0; k < 9; k++)
            wts[((n * 16 + pq) * 9 + k) * HW + hw] = v[k] * inv;
    }
}

// ------------- convex upsample + pixel shuffle ------------------------------
__global__ void upsample_kernel(const float* __restrict__ xp,
                                const float* __restrict__ wts,
                                float* __restrict__ up)
{
    constexpr int H = 128, W = 128, HW = H * W;
    __shared__ float s_xp[16][3][18];

    const int n = blockIdx.z, h = blockIdx.y, wtile = blockIdx.x * 16;
    const int tid = threadIdx.y * 64 + threadIdx.x;

    for (int i = tid; i < 16 * 3 * 18; i += 256) {
        int c = i / 54, rem = i % 54, r = rem / 18, col = rem % 18;
        int gh = h + r - 1, gw = wtile + col - 1;
        float v = 0.f;
        if (gh >= 0 && gh < H && gw >= 0 && gw < W)
            v = xp[(n * 16 + c) * HW + gh * W + gw];
        s_xp[c][r][col] = v;
    }
    __syncthreads();

    const int p  = threadIdx.y;
    const int q  = threadIdx.x & 3;
    const int wl = threadIdx.x >> 2;
    const int pq = p * 4 + q;
    const int hw = h * W + wtile + wl;

    float wt[9];
#pragma unroll
    for (int k = 0; k < 9; k++) wt[k] = wts[((n * 16 + pq) * 9 + k) * HW + hw];

    const int h_hi = h * 4 + p;
    const int w_hi = (wtile + wl) * 4 + q;
#pragma unroll
    for (int c = 0; c < 16; c++) {
        float acc = 0.f;
#pragma unroll
        for (int i = 0; i < 3; i++)
#pragma unroll
            for (int j = 0; j < 3; j++)
                acc = fmaf(wt[i * 3 + j], s_xp[c][i][wl + j], acc);
        up[((n * 16 + c) * 512 + h_hi) * 512 + w_hi] = acc;
    }
}

// ---------------------------------------------------------------------------
extern "C" void kernel_launch(void* const* d_in, const int* in_sizes, int n_in,
                              void* d_out, int out_size)
{
    const float* x     = (const float*)d_in[0];
    const float* p1_w1 = (const float*)d_in[1];
    const float* p1_b1 = (const float*)d_in[2];
    const float* p1_w2 = (const float*)d_in[3];
    const float* p1_b2 = (const float*)d_in[4];
    const float* gw_w1 = (const float*)d_in[5];
    const float* gw_b1 = (const float*)d_in[6];
    const float* gw_w2 = (const float*)d_in[7];
    const float* gw_b2 = (const float*)d_in[8];
    const float* p2_w1 = (const float*)d_in[9];
    const float* p2_b1 = (const float*)d_in[10];
    const float* p2_w2 = (const float*)d_in[11];
    const float* p2_b2 = (const float*)d_in[12];
    float* out = (float*)d_out;

    float *t1, *gg, *xp, *wts, *up, *mid;
    cudaGetSymbolAddress((void**)&t1,  g_t1);
    cudaGetSymbolAddress((void**)&gg,  g_g);
    cudaGetSymbolAddress((void**)&xp,  g_xp);
    cudaGetSymbolAddress((void**)&wts, g_wts);
    cudaGetSymbolAddress((void**)&up,  g_up);
    cudaGetSymbolAddress((void**)&mid, g_mid);

    dim3 b16(16, 16);

    // project1 conv1 (64->32, k3, ReLU): tile 64x16, CB=16 (2 groups)
    conv2d_kernel<64, 32, 16, 3, 4, true><<<dim3(2, 8, 16), b16>>>(x, p1_w1, p1_b1, t1, 128, 128);
    // guidance conv1 (64->32, k3, ReLU)
    conv2d_kernel<64, 32, 16, 3, 4, true><<<dim3(2, 8, 16), b16>>>(x, gw_w1, gw_b1, gg, 128, 128);
    // project1 conv2 (32->16, k3, ReLU)
    conv2d_kernel<32, 16, 16, 3, 4, true><<<dim3(2, 8, 8), b16>>>(t1, p1_w2, p1_b2, xp, 128, 128);
    // guidance 1x1 (32->144) + group softmax
    gw_softmax_kernel<<<512, 256>>>(gg, gw_w2, gw_b2, wts);
    // convex upsample + pixel shuffle -> (8,16,512,512)
    upsample_kernel<<<dim3(8, 128, 8), dim3(64, 4)>>>(xp, wts, up);
    // project2 conv1 (16->8, k5, ReLU) @512: tile 64x16, CB=8
    conv2d_kernel<16, 8, 8, 5, 4, true><<<dim3(8, 32, 8), b16>>>(up, p2_w1, p2_b1, mid, 512, 512);
    // project2 conv2 (8->64, k3) @512: tile 64x16, CB=16 (4 groups)
    conv2d_kernel<8, 64, 16, 3, 4, false><<<dim3(8, 32, 32), b16>>>(mid, p2_w2, p2_b2, out, 512, 512);
}

// round 6
// speedup vs baseline: 1.6938x; 1.6285x over previous
#include <cuda_runtime.h>

// ---------------- scratch (device globals; no allocations allowed) ----------
__device__ float g_t1 [8 * 32 * 128 * 128];      // project1 conv1 out (ReLU)
__device__ float g_g  [8 * 32 * 128 * 128];      // guidance conv1 out (ReLU)
__device__ float g_xp [8 * 16 * 128 * 128];      // project1 conv2 out (ReLU)
__device__ float g_wts[8 * 16 * 9 * 128 * 128];  // softmax weights (n, pq, k, hw)
__device__ float g_up [8 * 16 * 512 * 512];      // upsampled NCHW
__device__ float g_mid[8 *  8 * 512 * 512];      // project2 conv1 out (ReLU)

// ---------------- tf32 helpers ----------------------------------------------
__device__ __forceinline__ unsigned tf32_rna(float x) {
    unsigned r; asm("cvt.rna.tf32.f32 %0, %1;" : "=r"(r) : "f"(x)); return r;
}
__device__ __forceinline__ void mma_tf32(float& c0, float& c1, float& c2, float& c3,
                                         unsigned a0, unsigned a1, unsigned a2, unsigned a3,
                                         unsigned b0, unsigned b1) {
    asm volatile("mma.sync.aligned.m16n8k8.row.col.f32.tf32.tf32.f32 "
                 "{%0,%1,%2,%3}, {%4,%5,%6,%7}, {%8,%9}, {%0,%1,%2,%3};"
                 : "+f"(c0), "+f"(c1), "+f"(c2), "+f"(c3)
                 : "r"(a0), "r"(a1), "r"(a2), "r"(a3), "r"(b0), "r"(b1));
}

// ======================= round-2 scalar kernels (stage 1) ====================
template <int CIN, int COUT_TOTAL, int CB, int K, bool RELU>
__global__ __launch_bounds__(256, 2)
void conv2d_kernel(const float* __restrict__ in,
                   const float* __restrict__ wgt,
                   const float* __restrict__ bias,
                   float* __restrict__ out,
                   int H, int W)
{
    constexpr int TILE = 16;
    constexpr int S    = TILE + K - 1;
    constexpr int PAD  = K / 2;
    constexpr int KK   = K * K;
    constexpr int NGRP = COUT_TOTAL / CB;

    __shared__ float s_in[S * S];
    __shared__ float s_w[KK * CB];

    const int n   = blockIdx.z / NGRP;
    const int grp = blockIdx.z % NGRP;
    const int h0  = blockIdx.y * TILE;
    const int w0  = blockIdx.x * TILE;
    const int tx  = threadIdx.x, ty = threadIdx.y;
    const int tid = ty * TILE + tx;

    float acc[CB];
#pragma unroll
    for (int co = 0; co < CB; co++) acc[co] = bias[grp * CB + co];

    for (int cin = 0; cin < CIN; cin++) {
        __syncthreads();
        for (int i = tid; i < S * S; i += TILE * TILE) {
            int r = i / S, c = i % S;
            int gh = h0 + r - PAD, gw = w0 + c - PAD;
            float v = 0.f;
            if (gh >= 0 && gh < H && gw >= 0 && gw < W)
                v = in[((n * CIN + cin) * H + gh) * W + gw];
            s_in[i] = v;
        }
        for (int i = tid; i < KK * CB; i += TILE * TILE) {
            int co = i % CB, kidx = i / CB;
            s_w[i] = wgt[((grp * CB + co) * CIN + cin) * KK + kidx];
        }
        __syncthreads();

#pragma unroll
        for (int kh = 0; kh < K; kh++) {
#pragma unroll
            for (int kw = 0; kw < K; kw++) {
                float v = s_in[(ty + kh) * S + (tx + kw)];
                const float* wp = &s_w[(kh * K + kw) * CB];
#pragma unroll
                for (int co = 0; co < CB; co++)
                    acc[co] = fmaf(v, wp[co], acc[co]);
            }
        }
    }

    const int h = h0 + ty, w = w0 + tx;
#pragma unroll
    for (int co = 0; co < CB; co++) {
        float v = acc[co];
        if (RELU) v = fmaxf(v, 0.f);
        out[((n * COUT_TOTAL + grp * CB + co) * H + h) * W + w] = v;
    }
}

__global__ __launch_bounds__(256, 2)
void conv_dual64to32_kernel(const float* __restrict__ in,
                            const float* __restrict__ wA,
                            const float* __restrict__ bA,
                            float* __restrict__ outA,
                            const float* __restrict__ wB,
                            const float* __restrict__ bB,
                            float* __restrict__ outB)
{
    constexpr int H = 128, W = 128, TILE = 16, S = 18, CB = 32, CIN = 64;

    __shared__ float s_in[S * S];
    __shared__ float s_w[9 * CB];

    const int which = blockIdx.z & 1;
    const int n   = blockIdx.z >> 1;
    const float* wgt  = which ? wB : wA;
    const float* bias = which ? bB : bA;
    float*       out  = which ? outB : outA;

    const int h0 = blockIdx.y * TILE;
    const int w0 = blockIdx.x * TILE;
    const int tx = threadIdx.x, ty = threadIdx.y;
    const int tid = ty * TILE + tx;

    float acc[CB];
#pragma unroll
    for (int co = 0; co < CB; co++) acc[co] = bias[co];

    for (int cin = 0; cin < CIN; cin++) {
        __syncthreads();
        for (int i = tid; i < S * S; i += 256) {
            int r = i / S, c = i % S;
            int gh = h0 + r - 1, gw = w0 + c - 1;
            float v = 0.f;
            if (gh >= 0 && gh < H && gw >= 0 && gw < W)
                v = in[((n * CIN + cin) * H + gh) * W + gw];
            s_in[i] = v;
        }
        for (int i = tid; i < 9 * CB; i += 256) {
            int co = i % CB, kidx = i / CB;
            s_w[i] = wgt[(co * CIN + cin) * 9 + kidx];
        }
        __syncthreads();

#pragma unroll
        for (int kh = 0; kh < 3; kh++) {
#pragma unroll
            for (int kw = 0; kw < 3; kw++) {
                float v = s_in[(ty + kh) * S + (tx + kw)];
                const float* wp = &s_w[(kh * 3 + kw) * CB];
#pragma unroll
                for (int co = 0; co < CB; co++)
                    acc[co] = fmaf(v, wp[co], acc[co]);
            }
        }
    }

    const int h = h0 + ty, w = w0 + tx;
#pragma unroll
    for (int co = 0; co < CB; co++)
        out[((n * 32 + co) * H + h) * W + w] = fmaxf(acc[co], 0.f);
}

__global__ void gw_softmax_kernel(const float* __restrict__ g,
                                  const float* __restrict__ w2,
                                  const float* __restrict__ b2,
                                  float* __restrict__ wts)
{
    constexpr int HW = 128 * 128;
    __shared__ float s_w[144 * 32];
    __shared__ float s_b[144];
    for (int i = threadIdx.x; i < 144 * 32; i += 256) s_w[i] = w2[i];
    for (int i = threadIdx.x; i < 144;      i += 256) s_b[i] = b2[i];
    __syncthreads();

    const int pix = blockIdx.x * 256 + threadIdx.x;
    const int n = pix / HW, hw = pix % HW;

    float gv[32];
#pragma unroll
    for (int c = 0; c < 32; c++) gv[c] = g[(n * 32 + c) * HW + hw];

    for (int pq = 0; pq < 16; pq++) {
        float v[9];
#pragma unroll
        for (int k = 0; k < 9; k++) {
            const int ch = k * 16 + pq;
            float acc = s_b[ch];
            const float* wp = &s_w[ch * 32];
#pragma unroll
            for (int c = 0; c < 32; c++) acc = fmaf(gv[c], wp[c], acc);
            v[k] = acc;
        }
        float m = v[0];
#pragma unroll
        for (int k = 1; k < 9; k++) m = fmaxf(m, v[k]);
        float s = 0.f;
#pragma unroll
        for (int k = 0; k < 9; k++) { v[k] = __expf(v[k] - m); s += v[k]; }
        const float inv = 1.f / s;
#pragma unroll
        for (int k = 0; k < 9; k++)
            wts[((n * 16 + pq) * 9 + k) * HW + hw] = v[k] * inv;
    }
}

__global__ void upsample_kernel(const float* __restrict__ xp,
                                const float* __restrict__ wts,
                                float* __restrict__ up)
{
    constexpr int H = 128, W = 128, HW = H * W;
    __shared__ float s_xp[16][3][18];

    const int n = blockIdx.z, h = blockIdx.y, wtile = blockIdx.x * 16;
    const int tid = threadIdx.y * 64 + threadIdx.x;

    for (int i = tid; i < 16 * 3 * 18; i += 256) {
        int c = i / 54, rem = i % 54, r = rem / 18, col = rem % 18;
        int gh = h + r - 1, gw = wtile + col - 1;
        float v = 0.f;
        if (gh >= 0 && gh < H && gw >= 0 && gw < W)
            v = xp[(n * 16 + c) * HW + gh * W + gw];
        s_xp[c][r][col] = v;
    }
    __syncthreads();

    const int p  = threadIdx.y;
    const int q  = threadIdx.x & 3;
    const int wl = threadIdx.x >> 2;
    const int pq = p * 4 + q;
    const int hw = h * W + wtile + wl;

    float wt[9];
#pragma unroll
    for (int k = 0; k < 9; k++) wt[k] = wts[((n * 16 + pq) * 9 + k) * HW + hw];

    const int h_hi = h * 4 + p;
    const int w_hi = (wtile + wl) * 4 + q;
#pragma unroll
    for (int c = 0; c < 16; c++) {
        float acc = 0.f;
#pragma unroll
        for (int i = 0; i < 3; i++)
#pragma unroll
            for (int j = 0; j < 3; j++)
                acc = fmaf(wt[i * 3 + j], s_xp[c][i][wl + j], acc);
        up[((n * 16 + c) * 512 + h_hi) * 512 + w_hi] = acc;
    }
}

// ================= project2 conv1: 16->8, k5, ReLU, 512x512, tf32 MMA ========
// Block: 256 thr / 8 warps; tile = 4 rows x 64 cols; M=16 pix, N=8 co, K=8 cin.
// 3xTF32: D += ah*bh + ah*bl + al*bh.
__global__ __launch_bounds__(256)
void conv_p2a_mma(const float* __restrict__ in,   // g_up (8,16,512,512)
                  const float* __restrict__ wgt,  // (8,16,5,5)
                  const float* __restrict__ bias, // (8)
                  float* __restrict__ out)        // g_mid (8,8,512,512)
{
    constexpr int HW = 512;
    constexpr int CP = 69;                  // padded cols (>=68), CP odd -> plane%32==8
    constexpr int PLANE = 8 * CP;           // 552 ; 552 % 32 == 8 (bank-spread)
    extern __shared__ unsigned sm[];
    unsigned* s_hi = sm;                    // [16][8][CP]
    unsigned* s_lo = s_hi + 16 * PLANE;
    float*    s_w  = (float*)(s_lo + 16 * PLANE);   // 8*16*25 = 3200
    float*    s_b  = s_w + 3200;

    const int n  = blockIdx.z;
    const int h0 = blockIdx.y * 4;
    const int w0 = blockIdx.x * 64;
    const int tid = threadIdx.x;

    // fill input tile (rows h0-2..h0+5, cols w0-2..w0+65), split hi/lo
    for (int i = tid; i < 16 * 8 * 68; i += 256) {
        int cin = i / (8 * 68), rem = i % (8 * 68);
        int r = rem / 68, c = rem % 68;
        int gh = h0 + r - 2, gw = w0 + c - 2;
        float v = 0.f;
        if (gh >= 0 && gh < HW && gw >= 0 && gw < HW)
            v = in[((n * 16 + cin) * HW + gh) * HW + gw];
        unsigned hi = tf32_rna(v);
        float lo = v - __uint_as_float(hi);
        int a = cin * PLANE + r * CP + c;
        s_hi[a] = hi;
        s_lo[a] = tf32_rna(lo);
    }
    for (int i = tid; i < 3200; i += 256) s_w[i] = wgt[i];
    if (tid < 8) s_b[tid] = bias[tid];
    __syncthreads();

    const int warp = tid >> 5, lane = tid & 31;
    const int g = lane >> 2, t = lane & 3;

    float c[2][4];
#pragma unroll
    for (int t2 = 0; t2 < 2; t2++) {
        c[t2][0] = s_b[2 * t];     c[t2][1] = s_b[2 * t + 1];
        c[t2][2] = c[t2][0];       c[t2][3] = c[t2][1];
    }

#pragma unroll
    for (int dh = 0; dh < 5; dh++) {
#pragma unroll
        for (int dw = 0; dw < 5; dw++) {
            const int tap = dh * 5 + dw;
#pragma unroll
            for (int ch = 0; ch < 2; ch++) {
                float r0 = s_w[g * 400 + (ch * 8 + t) * 25 + tap];
                float r1 = s_w[g * 400 + (ch * 8 + t + 4) * 25 + tap];
                unsigned bh0 = tf32_rna(r0), bh1 = tf32_rna(r1);
                unsigned bl0 = tf32_rna(r0 - __uint_as_float(bh0));
                unsigned bl1 = tf32_rna(r1 - __uint_as_float(bh1));
#pragma unroll
                for (int t2 = 0; t2 < 2; t2++) {
                    const int id = warp + 8 * t2;
                    const int r = id >> 2, cs = id & 3;
                    const int base = (ch * 8 + t) * PLANE + (r + dh) * CP + cs * 16 + g + dw;
                    unsigned a0 = s_hi[base],             a1 = s_hi[base + 8];
                    unsigned a2 = s_hi[base + 4 * PLANE], a3 = s_hi[base + 4 * PLANE + 8];
                    unsigned l0 = s_lo[base],             l1 = s_lo[base + 8];
                    unsigned l2 = s_lo[base + 4 * PLANE], l3 = s_lo[base + 4 * PLANE + 8];
                    mma_tf32(c[t2][0], c[t2][1], c[t2][2], c[t2][3], a0, a1, a2, a3, bh0, bh1);
                    mma_tf32(c[t2][0], c[t2][1], c[t2][2], c[t2][3], a0, a1, a2, a3, bl0, bl1);
                    mma_tf32(c[t2][0], c[t2][1], c[t2][2], c[t2][3], l0, l1, l2, l3, bh0, bh1);
                }
            }
        }
    }

#pragma unroll
    for (int t2 = 0; t2 < 2; t2++) {
        const int id = warp + 8 * t2;
        const int r = id >> 2, cs = id & 3;
        const int h = h0 + r, w = w0 + cs * 16 + g;
        const int ob = ((n * 8 + 2 * t) * HW + h) * HW + w;
        out[ob]                = fmaxf(c[t2][0], 0.f);
        out[ob + HW * HW]      = fmaxf(c[t2][1], 0.f);
        out[ob + 8]            = fmaxf(c[t2][2], 0.f);
        out[ob + HW * HW + 8]  = fmaxf(c[t2][3], 0.f);
    }
}

// ================= project2 conv2: 8->64, k3, 512x512, tf32 MMA ==============
__global__ __launch_bounds__(256)
void conv_p2b_mma(const float* __restrict__ in,   // g_mid (8,8,512,512)
                  const float* __restrict__ wgt,  // (64,8,3,3)
                  const float* __restrict__ bias, // (64)
                  float* __restrict__ out)        // (8,64,512,512)
{
    constexpr int HW = 512;
    constexpr int CP = 68;                  // 6*68 = 408, 408 % 32 == 24 (bank-spread)
    constexpr int PLANE = 6 * CP;
    extern __shared__ unsigned sm[];
    unsigned* s_hi = sm;                    // [8][6][CP]
    unsigned* s_lo = s_hi + 8 * PLANE;
    float*    s_w  = (float*)(s_lo + 8 * PLANE);    // 64*8*9 = 4608
    float*    s_b  = s_w + 4608;

    const int n  = blockIdx.z;
    const int h0 = blockIdx.y * 4;
    const int w0 = blockIdx.x * 64;
    const int tid = threadIdx.x;

    for (int i = tid; i < 8 * 6 * 66; i += 256) {
        int cin = i / (6 * 66), rem = i % (6 * 66);
        int r = rem / 66, c = rem % 66;
        int gh = h0 + r - 1, gw = w0 + c - 1;
        float v = 0.f;
        if (gh >= 0 && gh < HW && gw >= 0 && gw < HW)
            v = in[((n * 8 + cin) * HW + gh) * HW + gw];
        unsigned hi = tf32_rna(v);
        float lo = v - __uint_as_float(hi);
        int a = cin * PLANE + r * CP + c;
        s_hi[a] = hi;
        s_lo[a] = tf32_rna(lo);
    }
    for (int i = tid; i < 4608; i += 256) s_w[i] = wgt[i];
    if (tid < 64) s_b[tid] = bias[tid];
    __syncthreads();

    const int warp = tid >> 5, lane = tid & 31;
    const int g = lane >> 2, t = lane & 3;

#pragma unroll 1
    for (int ct = 0; ct < 8; ct++) {
        // B fragments for all 9 taps, hi/lo
        unsigned bh[9][2], bl[9][2];
#pragma unroll
        for (int tap = 0; tap < 9; tap++) {
#pragma unroll
            for (int j = 0; j < 2; j++) {
                float raw = s_w[(ct * 8 + g) * 72 + (t + 4 * j) * 9 + tap];
                bh[tap][j] = tf32_rna(raw);
                bl[tap][j] = tf32_rna(raw - __uint_as_float(bh[tap][j]));
            }
        }
#pragma unroll
        for (int t2 = 0; t2 < 2; t2++) {
            const int id = warp + 8 * t2;
            const int r = id >> 2, cs = id & 3;
            float c0 = s_b[ct * 8 + 2 * t], c1 = s_b[ct * 8 + 2 * t + 1];
            float c2 = c0, c3 = c1;
#pragma unroll
            for (int dh = 0; dh < 3; dh++) {
#pragma unroll
                for (int dw = 0; dw < 3; dw++) {
                    const int tap = dh * 3 + dw;
                    const int base = t * PLANE + (r + dh) * CP + cs * 16 + g + dw;
                    unsigned a0 = s_hi[base],             a1 = s_hi[base + 8];
                    unsigned a2 = s_hi[base + 4 * PLANE], a3 = s_hi[base + 4 * PLANE + 8];
                    unsigned l0 = s_lo[base],             l1 = s_lo[base + 8];
                    unsigned l2 = s_lo[base + 4 * PLANE], l3 = s_lo[base + 4 * PLANE + 8];
                    mma_tf32(c0, c1, c2, c3, a0, a1, a2, a3, bh[tap][0], bh[tap][1]);
                    mma_tf32(c0, c1, c2, c3, a0, a1, a2, a3, bl[tap][0], bl[tap][1]);
                    mma_tf32(c0, c1, c2, c3, l0, l1, l2, l3, bh[tap][0], bh[tap][1]);
                }
            }
            const int h = h0 + r, w = w0 + cs * 16 + g;
            const int co = ct * 8 + 2 * t;
            const int ob = ((n * 64 + co) * HW + h) * HW + w;
            out[ob]               = c0;
            out[ob + HW * HW]     = c1;
            out[ob + 8]           = c2;
            out[ob + HW * HW + 8] = c3;
        }
    }
}

// ---------------------------------------------------------------------------
extern "C" void kernel_launch(void* const* d_in, const int* in_sizes, int n_in,
                              void* d_out, int out_size)
{
    const float* x     = (const float*)d_in[0];
    const float* p1_w1 = (const float*)d_in[1];
    const float* p1_b1 = (const float*)d_in[2];
    const float* p1_w2 = (const float*)d_in[3];
    const float* p1_b2 = (const float*)d_in[4];
    const float* gw_w1 = (const float*)d_in[5];
    const float* gw_b1 = (const float*)d_in[6];
    const float* gw_w2 = (const float*)d_in[7];
    const float* gw_b2 = (const float*)d_in[8];
    const float* p2_w1 = (const float*)d_in[9];
    const float* p2_b1 = (const float*)d_in[10];
    const float* p2_w2 = (const float*)d_in[11];
    const float* p2_b2 = (const float*)d_in[12];
    float* out = (float*)d_out;

    float *t1, *gg, *xp, *wts, *up, *mid;
    cudaGetSymbolAddress((void**)&t1,  g_t1);
    cudaGetSymbolAddress((void**)&gg,  g_g);
    cudaGetSymbolAddress((void**)&xp,  g_xp);
    cudaGetSymbolAddress((void**)&wts, g_wts);
    cudaGetSymbolAddress((void**)&up,  g_up);
    cudaGetSymbolAddress((void**)&mid, g_mid);

    // dynamic smem sizes for the tensor kernels
    const int SMEM_A = (16 * 8 * 69 * 2) * 4 + 3200 * 4 + 8 * 4;   // 83488 B
    const int SMEM_B = (8 * 6 * 68 * 2) * 4 + 4608 * 4 + 64 * 4;   // 44800 B
    static bool attr_done = false;
    cudaFuncSetAttribute(conv_p2a_mma, cudaFuncAttributeMaxDynamicSharedMemorySize, SMEM_A);
    cudaFuncSetAttribute(conv_p2b_mma, cudaFuncAttributeMaxDynamicSharedMemorySize, SMEM_B);
    (void)attr_done;

    dim3 b16(16, 16);

    // stage 1 (round-2 proven kernels)
    conv_dual64to32_kernel<<<dim3(8, 8, 16), b16>>>(x, p1_w1, p1_b1, t1,
                                                    gw_w1, gw_b1, gg);
    conv2d_kernel<32, 16, 16, 3, true><<<dim3(8, 8, 8), b16>>>(t1, p1_w2, p1_b2, xp, 128, 128);
    gw_softmax_kernel<<<512, 256>>>(gg, gw_w2, gw_b2, wts);
    upsample_kernel<<<dim3(8, 128, 8), dim3(64, 4)>>>(xp, wts, up);

    // project2 on tensor cores (tf32 x3)
    conv_p2a_mma<<<dim3(8, 128, 8), 256, SMEM_A>>>(up, p2_w1, p2_b1, mid);
    conv_p2b_mma<<<dim3(8, 128, 8), 256, SMEM_B>>>(mid, p2_w2, p2_b2, out);
}

// round 10
// speedup vs baseline: 2.1104x; 1.2460x over previous
#include <cuda_runtime.h>

// ---------------- scratch (device globals; no allocations allowed) ----------
__device__ float g_t1 [8 * 32 * 128 * 128];      // project1 conv1 out (ReLU)
__device__ float g_g  [8 * 32 * 128 * 128];      // guidance conv1 out (ReLU)
__device__ float g_xp [8 * 16 * 128 * 128];      // project1 conv2 out (ReLU)
__device__ float g_wts[8 * 16 * 9 * 128 * 128];  // softmax weights (n, pq, k, hw)
__device__ float g_up [8 * 16 * 512 * 512];      // upsampled NCHW
__device__ float g_mid[8 *  8 * 512 * 512];      // project2 conv1 out (ReLU)

// ---------------- tf32 helpers ----------------------------------------------
__device__ __forceinline__ unsigned tf32_rna(float x) {
    unsigned r; asm("cvt.rna.tf32.f32 %0, %1;" : "=r"(r) : "f"(x)); return r;
}
__device__ __forceinline__ void mma_tf32(float& c0, float& c1, float& c2, float& c3,
                                         unsigned a0, unsigned a1, unsigned a2, unsigned a3,
                                         unsigned b0, unsigned b1) {
    asm volatile("mma.sync.aligned.m16n8k8.row.col.f32.tf32.tf32.f32 "
                 "{%0,%1,%2,%3}, {%4,%5,%6,%7}, {%8,%9}, {%0,%1,%2,%3};"
                 : "+f"(c0), "+f"(c1), "+f"(c2), "+f"(c3)
                 : "r"(a0), "r"(a1), "r"(a2), "r"(a3), "r"(b0), "r"(b1));
}

// ======================= scalar conv (used for 32->16 only) ==================
template <int CIN, int COUT_TOTAL, int CB, int K, bool RELU>
__global__ __launch_bounds__(256, 2)
void conv2d_kernel(const float* __restrict__ in,
                   const float* __restrict__ wgt,
                   const float* __restrict__ bias,
                   float* __restrict__ out,
                   int H, int W)
{
    constexpr int TILE = 16;
    constexpr int S    = TILE + K - 1;
    constexpr int PAD  = K / 2;
    constexpr int KK   = K * K;
    constexpr int NGRP = COUT_TOTAL / CB;

    __shared__ float s_in[S * S];
    __shared__ float s_w[KK * CB];

    const int n   = blockIdx.z / NGRP;
    const int grp = blockIdx.z % NGRP;
    const int h0  = blockIdx.y * TILE;
    const int w0  = blockIdx.x * TILE;
    const int tx  = threadIdx.x, ty = threadIdx.y;
    const int tid = ty * TILE + tx;

    float acc[CB];
#pragma unroll
    for (int co = 0; co < CB; co++) acc[co] = bias[grp * CB + co];

    for (int cin = 0; cin < CIN; cin++) {
        __syncthreads();
        for (int i = tid; i < S * S; i += TILE * TILE) {
            int r = i / S, c = i % S;
            int gh = h0 + r - PAD, gw = w0 + c - PAD;
            float v = 0.f;
            if (gh >= 0 && gh < H && gw >= 0 && gw < W)
                v = in[((n * CIN + cin) * H + gh) * W + gw];
            s_in[i] = v;
        }
        for (int i = tid; i < KK * CB; i += TILE * TILE) {
            int co = i % CB, kidx = i / CB;
            s_w[i] = wgt[((grp * CB + co) * CIN + cin) * KK + kidx];
        }
        __syncthreads();

#pragma unroll
        for (int kh = 0; kh < K; kh++) {
#pragma unroll
            for (int kw = 0; kw < K; kw++) {
                float v = s_in[(ty + kh) * S + (tx + kw)];
                const float* wp = &s_w[(kh * K + kw) * CB];
#pragma unroll
                for (int co = 0; co < CB; co++)
                    acc[co] = fmaf(v, wp[co], acc[co]);
            }
        }
    }

    const int h = h0 + ty, w = w0 + tx;
#pragma unroll
    for (int co = 0; co < CB; co++) {
        float v = acc[co];
        if (RELU) v = fmaxf(v, 0.f);
        out[((n * COUT_TOTAL + grp * CB + co) * H + h) * W + w] = v;
    }
}

// ============ stage-1 dual 64->32 k3 ReLU via tf32 MMA (128x128) =============
// Tile: 4 rows x 64 cols. blockIdx.z: bit0 = which branch, rest = batch n.
// Cin processed in 8 chunks of 8. Weights pre-split to tf32 hi/lo in smem.
__global__ __launch_bounds__(256)
void conv_s1_mma(const float* __restrict__ in,
                 const float* __restrict__ wA, const float* __restrict__ bA,
                 float* __restrict__ outA,
                 const float* __restrict__ wB, const float* __restrict__ bB,
                 float* __restrict__ outB)
{
    constexpr int HW = 128;
    constexpr int CP = 68;                 // 66 needed; PLANE = 6*68 = 408 (%32==24)
    constexpr int PLANE = 6 * CP;
    extern __shared__ unsigned sm[];
    unsigned* s_hi = sm;                   // [8][6][CP]
    unsigned* s_lo = s_hi + 8 * PLANE;
    unsigned* s_wh = s_lo + 8 * PLANE;     // [32 co][8 ci][9 tap] tf32-hi
    unsigned* s_wl = s_wh + 2304;          // tf32-lo

    const int which = blockIdx.z & 1;
    const int n  = blockIdx.z >> 1;
    const float* wgt  = which ? wB : wA;
    const float* bias = which ? bB : bA;
    float*       out  = which ? outB : outA;

    const int h0 = blockIdx.y * 4;
    const int w0 = blockIdx.x * 64;
    const int tid = threadIdx.x;
    const int warp = tid >> 5, lane = tid & 31;
    const int g = lane >> 2, t = lane & 3;

    float acc[4][2][4];
#pragma unroll
    for (int ct = 0; ct < 4; ct++) {
        float b0 = bias[ct * 8 + 2 * t], b1 = bias[ct * 8 + 2 * t + 1];
#pragma unroll
        for (int t2 = 0; t2 < 2; t2++) {
            acc[ct][t2][0] = b0; acc[ct][t2][1] = b1;
            acc[ct][t2][2] = b0; acc[ct][t2][3] = b1;
        }
    }

#pragma unroll 1
    for (int chunk = 0; chunk < 8; chunk++) {
        __syncthreads();
        // input tile: 8 cin x 6 rows x 66 cols, split hi/lo
        for (int i = tid; i < 8 * 6 * 66; i += 256) {
            int ci = i / 396, rem = i % 396;
            int r = rem / 66, c = rem % 66;
            int gh = h0 + r - 1, gw = w0 + c - 1;
            float v = 0.f;
            if (gh >= 0 && gh < HW && gw >= 0 && gw < HW)
                v = in[((n * 64 + chunk * 8 + ci) * HW + gh) * HW + gw];
            unsigned hi = tf32_rna(v);
            int a = ci * PLANE + r * CP + c;
            s_hi[a] = hi;
            s_lo[a] = tf32_rna(v - __uint_as_float(hi));
        }
        // weights for this cin chunk: [co][ci][tap], pre-split hi/lo
        for (int i = tid; i < 2304; i += 256) {
            int co = i / 72, rem = i % 72;
            float raw = wgt[co * 576 + chunk * 72 + rem];
            unsigned hi = tf32_rna(raw);
            s_wh[i] = hi;
            s_wl[i] = tf32_rna(raw - __uint_as_float(hi));
        }
        __syncthreads();

#pragma unroll
        for (int dh = 0; dh < 3; dh++) {
#pragma unroll
            for (int dw = 0; dw < 3; dw++) {
                const int tap = dh * 3 + dw;
                unsigned A[2][8];
#pragma unroll
                for (int t2 = 0; t2 < 2; t2++) {
                    const int id = warp + 8 * t2;
                    const int r = id >> 2, cs = id & 3;
                    const int base = t * PLANE + (r + dh) * CP + cs * 16 + g + dw;
                    A[t2][0] = s_hi[base];             A[t2][1] = s_hi[base + 8];
                    A[t2][2] = s_hi[base + 4 * PLANE]; A[t2][3] = s_hi[base + 8 + 4 * PLANE];
                    A[t2][4] = s_lo[base];             A[t2][5] = s_lo[base + 8];
                    A[t2][6] = s_lo[base + 4 * PLANE]; A[t2][7] = s_lo[base + 8 + 4 * PLANE];
                }
#pragma unroll
                for (int ct = 0; ct < 4; ct++) {
                    const int wb = (ct * 8 + g) * 72 + tap;
                    unsigned bh0 = s_wh[wb + t * 9], bh1 = s_wh[wb + (t + 4) * 9];
                    unsigned bl0 = s_wl[wb + t * 9], bl1 = s_wl[wb + (t + 4) * 9];
#pragma unroll
                    for (int t2 = 0; t2 < 2; t2++) {
                        mma_tf32(acc[ct][t2][0], acc[ct][t2][1], acc[ct][t2][2], acc[ct][t2][3],
                                 A[t2][0], A[t2][1], A[t2][2], A[t2][3], bh0, bh1);
                        mma_tf32(acc[ct][t2][0], acc[ct][t2][1], acc[ct][t2][2], acc[ct][t2][3],
                                 A[t2][0], A[t2][1], A[t2][2], A[t2][3], bl0, bl1);
                        mma_tf32(acc[ct][t2][0], acc[ct][t2][1], acc[ct][t2][2], acc[ct][t2][3],
                                 A[t2][4], A[t2][5], A[t2][6], A[t2][7], bh0, bh1);
                    }
                }
            }
        }
    }

#pragma unroll
    for (int ct = 0; ct < 4; ct++) {
#pragma unroll
        for (int t2 = 0; t2 < 2; t2++) {
            const int id = warp + 8 * t2;
            const int r = id >> 2, cs = id & 3;
            const int h = h0 + r, w = w0 + cs * 16 + g;
            const int co = ct * 8 + 2 * t;
            const int ob = ((n * 32 + co) * HW + h) * HW + w;
            out[ob]               = fmaxf(acc[ct][t2][0], 0.f);
            out[ob + HW * HW]     = fmaxf(acc[ct][t2][1], 0.f);
            out[ob + 8]           = fmaxf(acc[ct][t2][2], 0.f);
            out[ob + HW * HW + 8] = fmaxf(acc[ct][t2][3], 0.f);
        }
    }
}

// ------------- guidance 1x1 conv (32->144) + per-(p,q) softmax over 9 -------
__global__ void gw_softmax_kernel(const float* __restrict__ g,
                                  const float* __restrict__ w2,
                                  const float* __restrict__ b2,
                                  float* __restrict__ wts)
{
    constexpr int HW = 128 * 128;
    __shared__ float s_w[144 * 32];
    __shared__ float s_b[144];
    for (int i = threadIdx.x; i < 144 * 32; i += 256) s_w[i] = w2[i];
    for (int i = threadIdx.x; i < 144;      i += 256) s_b[i] = b2[i];
    __syncthreads();

    const int pix = blockIdx.x * 256 + threadIdx.x;
    const int n = pix / HW, hw = pix % HW;

    float gv[32];
#pragma unroll
    for (int c = 0; c < 32; c++) gv[c] = g[(n * 32 + c) * HW + hw];

    for (int pq = 0; pq < 16; pq++) {
        float v[9];
#pragma unroll
        for (int k = 0; k < 9; k++) {
            const int ch = k * 16 + pq;
            float acc = s_b[ch];
            const float* wp = &s_w[ch * 32];
#pragma unroll
            for (int c = 0; c < 32; c++) acc = fmaf(gv[c], wp[c], acc);
            v[k] = acc;
        }
        float m = v[0];
#pragma unroll
        for (int k = 1; k < 9; k++) m = fmaxf(m, v[k]);
        float s = 0.f;
#pragma unroll
        for (int k = 0; k < 9; k++) { v[k] = __expf(v[k] - m); s += v[k]; }
        const float inv = 1.f / s;
#pragma unroll
        for (int k = 0; k < 9; k++)
            wts[((n * 16 + pq) * 9 + k) * HW + hw] = v[k] * inv;
    }
}

// ------------- convex upsample + pixel shuffle ------------------------------
__global__ void upsample_kernel(const float* __restrict__ xp,
                                const float* __restrict__ wts,
                                float* __restrict__ up)
{
    constexpr int H = 128, W = 128, HW = H * W;
    __shared__ float s_xp[16][3][18];

    const int n = blockIdx.z, h = blockIdx.y, wtile = blockIdx.x * 16;
    const int tid = threadIdx.y * 64 + threadIdx.x;

    for (int i = tid; i < 16 * 3 * 18; i += 256) {
        int c = i / 54, rem = i % 54, r = rem / 18, col = rem % 18;
        int gh = h + r - 1, gw = wtile + col - 1;
        float v = 0.f;
        if (gh >= 0 && gh < H && gw >= 0 && gw < W)
            v = xp[(n * 16 + c) * HW + gh * W + gw];
        s_xp[c][r][col] = v;
    }
    __syncthreads();

    const int p  = threadIdx.y;
    const int q  = threadIdx.x & 3;
    const int wl = threadIdx.x >> 2;
    const int pq = p * 4 + q;
    const int hw = h * W + wtile + wl;

    float wt[9];
#pragma unroll
    for (int k = 0; k < 9; k++) wt[k] = wts[((n * 16 + pq) * 9 + k) * HW + hw];

    const int h_hi = h * 4 + p;
    const int w_hi = (wtile + wl) * 4 + q;
#pragma unroll
    for (int c = 0; c < 16; c++) {
        float acc = 0.f;
#pragma unroll
        for (int i = 0; i < 3; i++)
#pragma unroll
            for (int j = 0; j < 3; j++)
                acc = fmaf(wt[i * 3 + j], s_xp[c][i][wl + j], acc);
        up[((n * 16 + c) * 512 + h_hi) * 512 + w_hi] = acc;
    }
}

// ================= project2 conv1: 16->8, k5, ReLU, 512x512, tf32 MMA ========
__global__ __launch_bounds__(256)
void conv_p2a_mma(const float* __restrict__ in,
                  const float* __restrict__ wgt,
                  const float* __restrict__ bias,
                  float* __restrict__ out)
{
    constexpr int HW = 512;
    constexpr int CP = 69;
    constexpr int PLANE = 8 * CP;
    extern __shared__ unsigned sm[];
    unsigned* s_hi = sm;
    unsigned* s_lo = s_hi + 16 * PLANE;
    float*    s_w  = (float*)(s_lo + 16 * PLANE);
    float*    s_b  = s_w + 3200;

    const int n  = blockIdx.z;
    const int h0 = blockIdx.y * 4;
    const int w0 = blockIdx.x * 64;
    const int tid = threadIdx.x;

    for (int i = tid; i < 16 * 8 * 68; i += 256) {
        int cin = i / (8 * 68), rem = i % (8 * 68);
        int r = rem / 68, c = rem % 68;
        int gh = h0 + r - 2, gw = w0 + c - 2;
        float v = 0.f;
        if (gh >= 0 && gh < HW && gw >= 0 && gw < HW)
            v = in[((n * 16 + cin) * HW + gh) * HW + gw];
        unsigned hi = tf32_rna(v);
        float lo = v - __uint_as_float(hi);
        int a = cin * PLANE + r * CP + c;
        s_hi[a] = hi;
        s_lo[a] = tf32_rna(lo);
    }
    for (int i = tid; i < 3200; i += 256) s_w[i] = wgt[i];
    if (tid < 8) s_b[tid] = bias[tid];
    __syncthreads();

    const int warp = tid >> 5, lane = tid & 31;
    const int g = lane >> 2, t = lane & 3;

    float c[2][4];
#pragma unroll
    for (int t2 = 0; t2 < 2; t2++) {
        c[t2][0] = s_b[2 * t];     c[t2][1] = s_b[2 * t + 1];
        c[t2][2] = c[t2][0];       c[t2][3] = c[t2][1];
    }

#pragma unroll
    for (int dh = 0; dh < 5; dh++) {
#pragma unroll
        for (int dw = 0; dw < 5; dw++) {
            const int tap = dh * 5 + dw;
#pragma unroll
            for (int ch = 0; ch < 2; ch++) {
                float r0 = s_w[g * 400 + (ch * 8 + t) * 25 + tap];
                float r1 = s_w[g * 400 + (ch * 8 + t + 4) * 25 + tap];
                unsigned bh0 = tf32_rna(r0), bh1 = tf32_rna(r1);
                unsigned bl0 = tf32_rna(r0 - __uint_as_float(bh0));
                unsigned bl1 = tf32_rna(r1 - __uint_as_float(bh1));
#pragma unroll
                for (int t2 = 0; t2 < 2; t2++) {
                    const int id = warp + 8 * t2;
                    const int r = id >> 2, cs = id & 3;
                    const int base = (ch * 8 + t) * PLANE + (r + dh) * CP + cs * 16 + g + dw;
                    unsigned a0 = s_hi[base],             a1 = s_hi[base + 8];
                    unsigned a2 = s_hi[base + 4 * PLANE], a3 = s_hi[base + 4 * PLANE + 8];
                    unsigned l0 = s_lo[base],             l1 = s_lo[base + 8];
                    unsigned l2 = s_lo[base + 4 * PLANE], l3 = s_lo[base + 4 * PLANE + 8];
                    mma_tf32(c[t2][0], c[t2][1], c[t2][2], c[t2][3], a0, a1, a2, a3, bh0, bh1);
                    mma_tf32(c[t2][0], c[t2][1], c[t2][2], c[t2][3], a0, a1, a2, a3, bl0, bl1);
                    mma_tf32(c[t2][0], c[t2][1], c[t2][2], c[t2][3], l0, l1, l2, l3, bh0, bh1);
                }
            }
        }
    }

#pragma unroll
    for (int t2 = 0; t2 < 2; t2++) {
        const int id = warp + 8 * t2;
        const int r = id >> 2, cs = id & 3;
        const int h = h0 + r, w = w0 + cs * 16 + g;
        const int ob = ((n * 8 + 2 * t) * HW + h) * HW + w;
        out[ob]                = fmaxf(c[t2][0], 0.f);
        out[ob + HW * HW]      = fmaxf(c[t2][1], 0.f);
        out[ob + 8]            = fmaxf(c[t2][2], 0.f);
        out[ob + HW * HW + 8]  = fmaxf(c[t2][3], 0.f);
    }
}

// ================= project2 conv2: 8->64, k3, 512x512, tf32 MMA ==============
__global__ __launch_bounds__(256)
void conv_p2b_mma(const float* __restrict__ in,
                  const float* __restrict__ wgt,
                  const float* __restrict__ bias,
                  float* __restrict__ out)
{
    constexpr int HW = 512;
    constexpr int CP = 68;
    constexpr int PLANE = 6 * CP;
    extern __shared__ unsigned sm[];
    unsigned* s_hi = sm;
    unsigned* s_lo = s_hi + 8 * PLANE;
    float*    s_w  = (float*)(s_lo + 8 * PLANE);
    float*    s_b  = s_w + 4608;

    const int n  = blockIdx.z;
    const int h0 = blockIdx.y * 4;
    const int w0 = blockIdx.x * 64;
    const int tid = threadIdx.x;

    for (int i = tid; i < 8 * 6 * 66; i += 256) {
        int cin = i / (6 * 66), rem = i % (6 * 66);
        int r = rem / 66, c = rem % 66;
        int gh = h0 + r - 1, gw = w0 + c - 1;
        float v = 0.f;
        if (gh >= 0 && gh < HW && gw >= 0 && gw < HW)
            v = in[((n * 8 + cin) * HW + gh) * HW + gw];
        unsigned hi = tf32_rna(v);
        float lo = v - __uint_as_float(hi);
        int a = cin * PLANE + r * CP + c;
        s_hi[a] = hi;
        s_lo[a] = tf32_rna(lo);
    }
    for (int i = tid; i < 4608; i += 256) s_w[i] = wgt[i];
    if (tid < 64) s_b[tid] = bias[tid];
    __syncthreads();

    const int warp = tid >> 5, lane = tid & 31;
    const int g = lane >> 2, t = lane & 3;

#pragma unroll 1
    for (int ct = 0; ct < 8; ct++) {
        unsigned bh[9][2], bl[9][2];
#pragma unroll
        for (int tap = 0; tap < 9; tap++) {
#pragma unroll
            for (int j = 0; j < 2; j++) {
                float raw = s_w[(ct * 8 + g) * 72 + (t + 4 * j) * 9 + tap];
                bh[tap][j] = tf32_rna(raw);
                bl[tap][j] = tf32_rna(raw - __uint_as_float(bh[tap][j]));
            }
        }
#pragma unroll
        for (int t2 = 0; t2 < 2; t2++) {
            const int id = warp + 8 * t2;
            const int r = id >> 2, cs = id & 3;
            float c0 = s_b[ct * 8 + 2 * t], c1 = s_b[ct * 8 + 2 * t + 1];
            float c2 = c0, c3 = c1;
#pragma unroll
            for (int dh = 0; dh < 3; dh++) {
#pragma unroll
                for (int dw = 0; dw < 3; dw++) {
                    const int tap = dh * 3 + dw;
                    const int base = t * PLANE + (r + dh) * CP + cs * 16 + g + dw;
                    unsigned a0 = s_hi[base],             a1 = s_hi[base + 8];
                    unsigned a2 = s_hi[base + 4 * PLANE], a3 = s_hi[base + 4 * PLANE + 8];
                    unsigned l0 = s_lo[base],             l1 = s_lo[base + 8];
                    unsigned l2 = s_lo[base + 4 * PLANE], l3 = s_lo[base + 4 * PLANE + 8];
                    mma_tf32(c0, c1, c2, c3, a0, a1, a2, a3, bh[tap][0], bh[tap][1]);
                    mma_tf32(c0, c1, c2, c3, a0, a1, a2, a3, bl[tap][0], bl[tap][1]);
                    mma_tf32(c0, c1, c2, c3, l0, l1, l2, l3, bh[tap][0], bh[tap][1]);
                }
            }
            const int h = h0 + r, w = w0 + cs * 16 + g;
            const int co = ct * 8 + 2 * t;
            const int ob = ((n * 64 + co) * HW + h) * HW + w;
            out[ob]               = c0;
            out[ob + HW * HW]     = c1;
            out[ob + 8]           = c2;
            out[ob + HW * HW + 8] = c3;
        }
    }
}

// ---------------------------------------------------------------------------
extern "C" void kernel_launch(void* const* d_in, const int* in_sizes, int n_in,
                              void* d_out, int out_size)
{
    const float* x     = (const float*)d_in[0];
    const float* p1_w1 = (const float*)d_in[1];
    const float* p1_b1 = (const float*)d_in[2];
    const float* p1_w2 = (const float*)d_in[3];
    const float* p1_b2 = (const float*)d_in[4];
    const float* gw_w1 = (const float*)d_in[5];
    const float* gw_b1 = (const float*)d_in[6];
    const float* gw_w2 = (const float*)d_in[7];
    const float* gw_b2 = (const float*)d_in[8];
    const float* p2_w1 = (const float*)d_in[9];
    const float* p2_b1 = (const float*)d_in[10];
    const float* p2_w2 = (const float*)d_in[11];
    const float* p2_b2 = (const float*)d_in[12];
    float* out = (float*)d_out;

    float *t1, *gg, *xp, *wts, *up, *mid;
    cudaGetSymbolAddress((void**)&t1,  g_t1);
    cudaGetSymbolAddress((void**)&gg,  g_g);
    cudaGetSymbolAddress((void**)&xp,  g_xp);
    cudaGetSymbolAddress((void**)&wts, g_wts);
    cudaGetSymbolAddress((void**)&up,  g_up);
    cudaGetSymbolAddress((void**)&mid, g_mid);

    const int SMEM_S1 = (8 * 408 * 2) * 4 + 2304 * 2 * 4;          // 44544 B
    const int SMEM_A  = (16 * 8 * 69 * 2) * 4 + 3200 * 4 + 8 * 4;  // 83488 B
    const int SMEM_B  = (8 * 6 * 68 * 2) * 4 + 4608 * 4 + 64 * 4;  // 44800 B
    cudaFuncSetAttribute(conv_s1_mma,  cudaFuncAttributeMaxDynamicSharedMemorySize, SMEM_S1);
    cudaFuncSetAttribute(conv_p2a_mma, cudaFuncAttributeMaxDynamicSharedMemorySize, SMEM_A);
    cudaFuncSetAttribute(conv_p2b_mma, cudaFuncAttributeMaxDynamicSharedMemorySize, SMEM_B);

    dim3 b16(16, 16);

    // stage 1: dual 64->32 k3 ReLU on tensor cores
    conv_s1_mma<<<dim3(2, 32, 16), 256, SMEM_S1>>>(x, p1_w1, p1_b1, t1,
                                                   gw_w1, gw_b1, gg);
    // project1 conv2 (32->16, k3, ReLU) scalar
    conv2d_kernel<32, 16, 16, 3, true><<<dim3(8, 8, 8), b16>>>(t1, p1_w2, p1_b2, xp, 128, 128);
    gw_softmax_kernel<<<512, 256>>>(gg, gw_w2, gw_b2, wts);
    upsample_kernel<<<dim3(8, 128, 8), dim3(64, 4)>>>(xp, wts, up);

    // project2 on tensor cores (tf32 x3)
    conv_p2a_mma<<<dim3(8, 128, 8), 256, SMEM_A>>>(up, p2_w1, p2_b1, mid);
    conv_p2b_mma<<<dim3(8, 128, 8), 256, SMEM_B>>>(mid, p2_w2, p2_b2, out);
}

// round 11
// speedup vs baseline: 2.2004x; 1.0426x over previous
#include <cuda_runtime.h>

// ---------------- scratch (device globals; no allocations allowed) ----------
__device__ float g_t1 [8 * 32 * 128 * 128];      // project1 conv1 out (ReLU)
__device__ float g_g  [8 * 32 * 128 * 128];      // guidance conv1 out (ReLU)
__device__ float g_xp [8 * 16 * 128 * 128];      // project1 conv2 out (ReLU)
__device__ float g_wts[8 * 16 * 9 * 128 * 128];  // softmax weights (n, pq, k, hw)
__device__ float g_up [8 * 16 * 512 * 512];      // upsampled NCHW
__device__ float g_mid[8 *  8 * 512 * 512];      // project2 conv1 out (ReLU)

// ---------------- tf32 helpers ----------------------------------------------
__device__ __forceinline__ unsigned tf32_rna(float x) {
    unsigned r; asm("cvt.rna.tf32.f32 %0, %1;" : "=r"(r) : "f"(x)); return r;
}
__device__ __forceinline__ void mma_tf32(float& c0, float& c1, float& c2, float& c3,
                                         unsigned a0, unsigned a1, unsigned a2, unsigned a3,
                                         unsigned b0, unsigned b1) {
    asm volatile("mma.sync.aligned.m16n8k8.row.col.f32.tf32.tf32.f32 "
                 "{%0,%1,%2,%3}, {%4,%5,%6,%7}, {%8,%9}, {%0,%1,%2,%3};"
                 : "+f"(c0), "+f"(c1), "+f"(c2), "+f"(c3)
                 : "r"(a0), "r"(a1), "r"(a2), "r"(a3), "r"(b0), "r"(b1));
}

// ======================= scalar conv (used for 32->16 only) ==================
template <int CIN, int COUT_TOTAL, int CB, int K, bool RELU>
__global__ __launch_bounds__(256, 2)
void conv2d_kernel(const float* __restrict__ in,
                   const float* __restrict__ wgt,
                   const float* __restrict__ bias,
                   float* __restrict__ out,
                   int H, int W)
{
    constexpr int TILE = 16;
    constexpr int S    = TILE + K - 1;
    constexpr int PAD  = K / 2;
    constexpr int KK   = K * K;
    constexpr int NGRP = COUT_TOTAL / CB;

    __shared__ float s_in[S * S];
    __shared__ float s_w[KK * CB];

    const int n   = blockIdx.z / NGRP;
    const int grp = blockIdx.z % NGRP;
    const int h0  = blockIdx.y * TILE;
    const int w0  = blockIdx.x * TILE;
    const int tx  = threadIdx.x, ty = threadIdx.y;
    const int tid = ty * TILE + tx;

    float acc[CB];
#pragma unroll
    for (int co = 0; co < CB; co++) acc[co] = bias[grp * CB + co];

    for (int cin = 0; cin < CIN; cin++) {
        __syncthreads();
        for (int i = tid; i < S * S; i += TILE * TILE) {
            int r = i / S, c = i % S;
            int gh = h0 + r - PAD, gw = w0 + c - PAD;
            float v = 0.f;
            if (gh >= 0 && gh < H && gw >= 0 && gw < W)
                v = in[((n * CIN + cin) * H + gh) * W + gw];
            s_in[i] = v;
        }
        for (int i = tid; i < KK * CB; i += TILE * TILE) {
            int co = i % CB, kidx = i / CB;
            s_w[i] = wgt[((grp * CB + co) * CIN + cin) * KK + kidx];
        }
        __syncthreads();

#pragma unroll
        for (int kh = 0; kh < K; kh++) {
#pragma unroll
            for (int kw = 0; kw < K; kw++) {
                float v = s_in[(ty + kh) * S + (tx + kw)];
                const float* wp = &s_w[(kh * K + kw) * CB];
#pragma unroll
                for (int co = 0; co < CB; co++)
                    acc[co] = fmaf(v, wp[co], acc[co]);
            }
        }
    }

    const int h = h0 + ty, w = w0 + tx;
#pragma unroll
    for (int co = 0; co < CB; co++) {
        float v = acc[co];
        if (RELU) v = fmaxf(v, 0.f);
        out[((n * COUT_TOTAL + grp * CB + co) * H + h) * W + w] = v;
    }
}

// ============ stage-1 dual 64->32 k3 ReLU via tf32 MMA (128x128) =============
__global__ __launch_bounds__(256)
void conv_s1_mma(const float* __restrict__ in,
                 const float* __restrict__ wA, const float* __restrict__ bA,
                 float* __restrict__ outA,
                 const float* __restrict__ wB, const float* __restrict__ bB,
                 float* __restrict__ outB)
{
    constexpr int HW = 128;
    constexpr int CP = 68;
    constexpr int PLANE = 6 * CP;
    extern __shared__ unsigned sm[];
    unsigned* s_hi = sm;                   // [8][6][CP]
    unsigned* s_lo = s_hi + 8 * PLANE;
    unsigned* s_wh = s_lo + 8 * PLANE;     // [32 co][8 ci][9 tap]
    unsigned* s_wl = s_wh + 2304;

    const int which = blockIdx.z & 1;
    const int n  = blockIdx.z >> 1;
    const float* wgt  = which ? wB : wA;
    const float* bias = which ? bB : bA;
    float*       out  = which ? outB : outA;

    const int h0 = blockIdx.y * 4;
    const int w0 = blockIdx.x * 64;
    const int tid = threadIdx.x;
    const int warp = tid >> 5, lane = tid & 31;
    const int g = lane >> 2, t = lane & 3;

    float acc[4][2][4];
#pragma unroll
    for (int ct = 0; ct < 4; ct++) {
        float b0 = bias[ct * 8 + 2 * t], b1 = bias[ct * 8 + 2 * t + 1];
#pragma unroll
        for (int t2 = 0; t2 < 2; t2++) {
            acc[ct][t2][0] = b0; acc[ct][t2][1] = b1;
            acc[ct][t2][2] = b0; acc[ct][t2][3] = b1;
        }
    }

#pragma unroll 1
    for (int chunk = 0; chunk < 8; chunk++) {
        __syncthreads();
        for (int i = tid; i < 8 * 6 * 66; i += 256) {
            int ci = i / 396, rem = i % 396;
            int r = rem / 66, c = rem % 66;
            int gh = h0 + r - 1, gw = w0 + c - 1;
            float v = 0.f;
            if (gh >= 0 && gh < HW && gw >= 0 && gw < HW)
                v = in[((n * 64 + chunk * 8 + ci) * HW + gh) * HW + gw];
            unsigned hi = tf32_rna(v);
            int a = ci * PLANE + r * CP + c;
            s_hi[a] = hi;
            s_lo[a] = tf32_rna(v - __uint_as_float(hi));
        }
        for (int i = tid; i < 2304; i += 256) {
            int co = i / 72, rem = i % 72;
            float raw = wgt[co * 576 + chunk * 72 + rem];
            unsigned hi = tf32_rna(raw);
            s_wh[i] = hi;
            s_wl[i] = tf32_rna(raw - __uint_as_float(hi));
        }
        __syncthreads();

#pragma unroll
        for (int dh = 0; dh < 3; dh++) {
#pragma unroll
            for (int dw = 0; dw < 3; dw++) {
                const int tap = dh * 3 + dw;
                unsigned A[2][8];
#pragma unroll
                for (int t2 = 0; t2 < 2; t2++) {
                    const int id = warp + 8 * t2;
                    const int r = id >> 2, cs = id & 3;
                    const int base = t * PLANE + (r + dh) * CP + cs * 16 + g + dw;
                    A[t2][0] = s_hi[base];             A[t2][1] = s_hi[base + 8];
                    A[t2][2] = s_hi[base + 4 * PLANE]; A[t2][3] = s_hi[base + 8 + 4 * PLANE];
                    A[t2][4] = s_lo[base];             A[t2][5] = s_lo[base + 8];
                    A[t2][6] = s_lo[base + 4 * PLANE]; A[t2][7] = s_lo[base + 8 + 4 * PLANE];
                }
#pragma unroll
                for (int ct = 0; ct < 4; ct++) {
                    const int wb = (ct * 8 + g) * 72 + tap;
                    unsigned bh0 = s_wh[wb + t * 9], bh1 = s_wh[wb + (t + 4) * 9];
                    unsigned bl0 = s_wl[wb + t * 9], bl1 = s_wl[wb + (t + 4) * 9];
#pragma unroll
                    for (int t2 = 0; t2 < 2; t2++) {
                        mma_tf32(acc[ct][t2][0], acc[ct][t2][1], acc[ct][t2][2], acc[ct][t2][3],
                                 A[t2][0], A[t2][1], A[t2][2], A[t2][3], bh0, bh1);
                        mma_tf32(acc[ct][t2][0], acc[ct][t2][1], acc[ct][t2][2], acc[ct][t2][3],
                                 A[t2][0], A[t2][1], A[t2][2], A[t2][3], bl0, bl1);
                        mma_tf32(acc[ct][t2][0], acc[ct][t2][1], acc[ct][t2][2], acc[ct][t2][3],
                                 A[t2][4], A[t2][5], A[t2][6], A[t2][7], bh0, bh1);
                    }
                }
            }
        }
    }

#pragma unroll
    for (int ct = 0; ct < 4; ct++) {
#pragma unroll
        for (int t2 = 0; t2 < 2; t2++) {
            const int id = warp + 8 * t2;
            const int r = id >> 2, cs = id & 3;
            const int h = h0 + r, w = w0 + cs * 16 + g;
            const int co = ct * 8 + 2 * t;
            const int ob = ((n * 32 + co) * HW + h) * HW + w;
            out[ob]               = fmaxf(acc[ct][t2][0], 0.f);
            out[ob + HW * HW]     = fmaxf(acc[ct][t2][1], 0.f);
            out[ob + 8]           = fmaxf(acc[ct][t2][2], 0.f);
            out[ob + HW * HW + 8] = fmaxf(acc[ct][t2][3], 0.f);
        }
    }
}

// ------------- guidance 1x1 conv (32->144) + per-(p,q) softmax over 9 -------
__global__ void gw_softmax_kernel(const float* __restrict__ g,
                                  const float* __restrict__ w2,
                                  const float* __restrict__ b2,
                                  float* __restrict__ wts)
{
    constexpr int HW = 128 * 128;
    __shared__ float s_w[144 * 32];
    __shared__ float s_b[144];
    for (int i = threadIdx.x; i < 144 * 32; i += 256) s_w[i] = w2[i];
    for (int i = threadIdx.x; i < 144;      i += 256) s_b[i] = b2[i];
    __syncthreads();

    const int pix = blockIdx.x * 256 + threadIdx.x;
    const int n = pix / HW, hw = pix % HW;

    float gv[32];
#pragma unroll
    for (int c = 0; c < 32; c++) gv[c] = g[(n * 32 + c) * HW + hw];

    for (int pq = 0; pq < 16; pq++) {
        float v[9];
#pragma unroll
        for (int k = 0; k < 9; k++) {
            const int ch = k * 16 + pq;
            float acc = s_b[ch];
            const float* wp = &s_w[ch * 32];
#pragma unroll
            for (int c = 0; c < 32; c++) acc = fmaf(gv[c], wp[c], acc);
            v[k] = acc;
        }
        float m = v[0];
#pragma unroll
        for (int k = 1; k < 9; k++) m = fmaxf(m, v[k]);
        float s = 0.f;
#pragma unroll
        for (int k = 0; k < 9; k++) { v[k] = __expf(v[k] - m); s += v[k]; }
        const float inv = 1.f / s;
#pragma unroll
        for (int k = 0; k < 9; k++)
            wts[((n * 16 + pq) * 9 + k) * HW + hw] = v[k] * inv;
    }
}

// ------------- convex upsample + pixel shuffle ------------------------------
__global__ void upsample_kernel(const float* __restrict__ xp,
                                const float* __restrict__ wts,
                                float* __restrict__ up)
{
    constexpr int H = 128, W = 128, HW = H * W;
    __shared__ float s_xp[16][3][18];

    const int n = blockIdx.z, h = blockIdx.y, wtile = blockIdx.x * 16;
    const int tid = threadIdx.y * 64 + threadIdx.x;

    for (int i = tid; i < 16 * 3 * 18; i += 256) {
        int c = i / 54, rem = i % 54, r = rem / 18, col = rem % 18;
        int gh = h + r - 1, gw = wtile + col - 1;
        float v = 0.f;
        if (gh >= 0 && gh < H && gw >= 0 && gw < W)
            v = xp[(n * 16 + c) * HW + gh * W + gw];
        s_xp[c][r][col] = v;
    }
    __syncthreads();

    const int p  = threadIdx.y;
    const int q  = threadIdx.x & 3;
    const int wl = threadIdx.x >> 2;
    const int pq = p * 4 + q;
    const int hw = h * W + wtile + wl;

    float wt[9];
#pragma unroll
    for (int k = 0; k < 9; k++) wt[k] = wts[((n * 16 + pq) * 9 + k) * HW + hw];

    const int h_hi = h * 4 + p;
    const int w_hi = (wtile + wl) * 4 + q;
#pragma unroll
    for (int c = 0; c < 16; c++) {
        float acc = 0.f;
#pragma unroll
        for (int i = 0; i < 3; i++)
#pragma unroll
            for (int j = 0; j < 3; j++)
                acc = fmaf(wt[i * 3 + j], s_xp[c][i][wl + j], acc);
        up[((n * 16 + c) * 512 + h_hi) * 512 + w_hi] = acc;
    }
}

// ================= project2 conv1: 16->8, k5, ReLU, 512x512, tf32 MMA ========
// Weights pre-split to tf32 hi/lo in smem (no cvt in hot loop).
__global__ __launch_bounds__(256)
void conv_p2a_mma(const float* __restrict__ in,
                  const float* __restrict__ wgt,
                  const float* __restrict__ bias,
                  float* __restrict__ out)
{
    constexpr int HW = 512;
    constexpr int CP = 69;
    constexpr int PLANE = 8 * CP;
    extern __shared__ unsigned sm[];
    unsigned* s_hi = sm;                    // 16*PLANE
    unsigned* s_lo = s_hi + 16 * PLANE;
    unsigned* s_wh = s_lo + 16 * PLANE;     // 3200
    unsigned* s_wl = s_wh + 3200;           // 3200
    float*    s_b  = (float*)(s_wl + 3200);

    const int n  = blockIdx.z;
    const int h0 = blockIdx.y * 4;
    const int w0 = blockIdx.x * 64;
    const int tid = threadIdx.x;

    for (int i = tid; i < 16 * 8 * 68; i += 256) {
        int cin = i / (8 * 68), rem = i % (8 * 68);
        int r = rem / 68, c = rem % 68;
        int gh = h0 + r - 2, gw = w0 + c - 2;
        float v = 0.f;
        if (gh >= 0 && gh < HW && gw >= 0 && gw < HW)
            v = in[((n * 16 + cin) * HW + gh) * HW + gw];
        unsigned hi = tf32_rna(v);
        float lo = v - __uint_as_float(hi);
        int a = cin * PLANE + r * CP + c;
        s_hi[a] = hi;
        s_lo[a] = tf32_rna(lo);
    }
    for (int i = tid; i < 3200; i += 256) {
        float raw = wgt[i];
        unsigned hi = tf32_rna(raw);
        s_wh[i] = hi;
        s_wl[i] = tf32_rna(raw - __uint_as_float(hi));
    }
    if (tid < 8) s_b[tid] = bias[tid];
    __syncthreads();

    const int warp = tid >> 5, lane = tid & 31;
    const int g = lane >> 2, t = lane & 3;

    float c[2][4];
#pragma unroll
    for (int t2 = 0; t2 < 2; t2++) {
        c[t2][0] = s_b[2 * t];     c[t2][1] = s_b[2 * t + 1];
        c[t2][2] = c[t2][0];       c[t2][3] = c[t2][1];
    }

#pragma unroll
    for (int dh = 0; dh < 5; dh++) {
#pragma unroll
        for (int dw = 0; dw < 5; dw++) {
            const int tap = dh * 5 + dw;
#pragma unroll
            for (int ch = 0; ch < 2; ch++) {
                const int wb0 = g * 400 + (ch * 8 + t) * 25 + tap;
                const int wb1 = g * 400 + (ch * 8 + t + 4) * 25 + tap;
                unsigned bh0 = s_wh[wb0], bh1 = s_wh[wb1];
                unsigned bl0 = s_wl[wb0], bl1 = s_wl[wb1];
#pragma unroll
                for (int t2 = 0; t2 < 2; t2++) {
                    const int id = warp + 8 * t2;
                    const int r = id >> 2, cs = id & 3;
                    const int base = (ch * 8 + t) * PLANE + (r + dh) * CP + cs * 16 + g + dw;
                    unsigned a0 = s_hi[base],             a1 = s_hi[base + 8];
                    unsigned a2 = s_hi[base + 4 * PLANE], a3 = s_hi[base + 4 * PLANE + 8];
                    unsigned l0 = s_lo[base],             l1 = s_lo[base + 8];
                    unsigned l2 = s_lo[base + 4 * PLANE], l3 = s_lo[base + 4 * PLANE + 8];
                    mma_tf32(c[t2][0], c[t2][1], c[t2][2], c[t2][3], a0, a1, a2, a3, bh0, bh1);
                    mma_tf32(c[t2][0], c[t2][1], c[t2][2], c[t2][3], a0, a1, a2, a3, bl0, bl1);
                    mma_tf32(c[t2][0], c[t2][1], c[t2][2], c[t2][3], l0, l1, l2, l3, bh0, bh1);
                }
            }
        }
    }

#pragma unroll
    for (int t2 = 0; t2 < 2; t2++) {
        const int id = warp + 8 * t2;
        const int r = id >> 2, cs = id & 3;
        const int h = h0 + r, w = w0 + cs * 16 + g;
        const int ob = ((n * 8 + 2 * t) * HW + h) * HW + w;
        out[ob]                = fmaxf(c[t2][0], 0.f);
        out[ob + HW * HW]      = fmaxf(c[t2][1], 0.f);
        out[ob + 8]            = fmaxf(c[t2][2], 0.f);
        out[ob + HW * HW + 8]  = fmaxf(c[t2][3], 0.f);
    }
}

// ================= project2 conv2: 8->64, k3, 512x512, tf32 MMA ==============
// Restructured: 2 passes of 4 co-groups, A fragments hoisted per tap,
// weights pre-split hi/lo in smem.
__global__ __launch_bounds__(256)
void conv_p2b_mma(const float* __restrict__ in,
                  const float* __restrict__ wgt,
                  const float* __restrict__ bias,
                  float* __restrict__ out)
{
    constexpr int HW = 512;
    constexpr int CP = 68;
    constexpr int PLANE = 6 * CP;
    extern __shared__ unsigned sm[];
    unsigned* s_hi = sm;                    // 8*PLANE
    unsigned* s_lo = s_hi + 8 * PLANE;
    unsigned* s_wh = s_lo + 8 * PLANE;      // 4608
    unsigned* s_wl = s_wh + 4608;           // 4608
    float*    s_b  = (float*)(s_wl + 4608); // 64

    const int n  = blockIdx.z;
    const int h0 = blockIdx.y * 4;
    const int w0 = blockIdx.x * 64;
    const int tid = threadIdx.x;

    for (int i = tid; i < 8 * 6 * 66; i += 256) {
        int cin = i / (6 * 66), rem = i % (6 * 66);
        int r = rem / 66, c = rem % 66;
        int gh = h0 + r - 1, gw = w0 + c - 1;
        float v = 0.f;
        if (gh >= 0 && gh < HW && gw >= 0 && gw < HW)
            v = in[((n * 8 + cin) * HW + gh) * HW + gw];
        unsigned hi = tf32_rna(v);
        float lo = v - __uint_as_float(hi);
        int a = cin * PLANE + r * CP + c;
        s_hi[a] = hi;
        s_lo[a] = tf32_rna(lo);
    }
    for (int i = tid; i < 4608; i += 256) {
        float raw = wgt[i];
        unsigned hi = tf32_rna(raw);
        s_wh[i] = hi;
        s_wl[i] = tf32_rna(raw - __uint_as_float(hi));
    }
    if (tid < 64) s_b[tid] = bias[tid];
    __syncthreads();

    const int warp = tid >> 5, lane = tid & 31;
    const int g = lane >> 2, t = lane & 3;

#pragma unroll 1
    for (int half = 0; half < 2; half++) {
        float acc[4][2][4];
#pragma unroll
        for (int c4 = 0; c4 < 4; c4++) {
            const int ct = half * 4 + c4;
            float b0 = s_b[ct * 8 + 2 * t], b1 = s_b[ct * 8 + 2 * t + 1];
#pragma unroll
            for (int t2 = 0; t2 < 2; t2++) {
                acc[c4][t2][0] = b0; acc[c4][t2][1] = b1;
                acc[c4][t2][2] = b0; acc[c4][t2][3] = b1;
            }
        }

#pragma unroll
        for (int dh = 0; dh < 3; dh++) {
#pragma unroll
            for (int dw = 0; dw < 3; dw++) {
                const int tap = dh * 3 + dw;
                unsigned A[2][8];
#pragma unroll
                for (int t2 = 0; t2 < 2; t2++) {
                    const int id = warp + 8 * t2;
                    const int r = id >> 2, cs = id & 3;
                    const int base = t * PLANE + (r + dh) * CP + cs * 16 + g + dw;
                    A[t2][0] = s_hi[base];             A[t2][1] = s_hi[base + 8];
                    A[t2][2] = s_hi[base + 4 * PLANE]; A[t2][3] = s_hi[base + 8 + 4 * PLANE];
                    A[t2][4] = s_lo[base];             A[t2][5] = s_lo[base + 8];
                    A[t2][6] = s_lo[base + 4 * PLANE]; A[t2][7] = s_lo[base + 8 + 4 * PLANE];
                }
#pragma unroll
                for (int c4 = 0; c4 < 4; c4++) {
                    const int ct = half * 4 + c4;
                    const int wb = (ct * 8 + g) * 72 + tap;
                    unsigned bh0 = s_wh[wb + t * 9], bh1 = s_wh[wb + (t + 4) * 9];
                    unsigned bl0 = s_wl[wb + t * 9], bl1 = s_wl[wb + (t + 4) * 9];
#pragma unroll
                    for (int t2 = 0; t2 < 2; t2++) {
                        mma_tf32(acc[c4][t2][0], acc[c4][t2][1], acc[c4][t2][2], acc[c4][t2][3],
                                 A[t2][0], A[t2][1], A[t2][2], A[t2][3], bh0, bh1);
                        mma_tf32(acc[c4][t2][0], acc[c4][t2][1], acc[c4][t2][2], acc[c4][t2][3],
                                 A[t2][0], A[t2][1], A[t2][2], A[t2][3], bl0, bl1);
                        mma_tf32(acc[c4][t2][0], acc[c4][t2][1], acc[c4][t2][2], acc[c4][t2][3],
                                 A[t2][4], A[t2][5], A[t2][6], A[t2][7], bh0, bh1);
                    }
                }
            }
        }

#pragma unroll
        for (int c4 = 0; c4 < 4; c4++) {
#pragma unroll
            for (int t2 = 0; t2 < 2; t2++) {
                const int id = warp + 8 * t2;
                const int r = id >> 2, cs = id & 3;
                const int h = h0 + r, w = w0 + cs * 16 + g;
                const int co = (half * 4 + c4) * 8 + 2 * t;
                const int ob = ((n * 64 + co) * HW + h) * HW + w;
                out[ob]               = acc[c4][t2][0];
                out[ob + HW * HW]     = acc[c4][t2][1];
                out[ob + 8]           = acc[c4][t2][2];
                out[ob + HW * HW + 8] = acc[c4][t2][3];
            }
        }
    }
}

// ---------------------------------------------------------------------------
extern "C" void kernel_launch(void* const* d_in, const int* in_sizes, int n_in,
                              void* d_out, int out_size)
{
    const float* x     = (const float*)d_in[0];
    const float* p1_w1 = (const float*)d_in[1];
    const float* p1_b1 = (const float*)d_in[2];
    const float* p1_w2 = (const float*)d_in[3];
    const float* p1_b2 = (const float*)d_in[4];
    const float* gw_w1 = (const float*)d_in[5];
    const float* gw_b1 = (const float*)d_in[6];
    const float* gw_w2 = (const float*)d_in[7];
    const float* gw_b2 = (const float*)d_in[8];
    const float* p2_w1 = (const float*)d_in[9];
    const float* p2_b1 = (const float*)d_in[10];
    const float* p2_w2 = (const float*)d_in[11];
    const float* p2_b2 = (const float*)d_in[12];
    float* out = (float*)d_out;

    float *t1, *gg, *xp, *wts, *up, *mid;
    cudaGetSymbolAddress((void**)&t1,  g_t1);
    cudaGetSymbolAddress((void**)&gg,  g_g);
    cudaGetSymbolAddress((void**)&xp,  g_xp);
    cudaGetSymbolAddress((void**)&wts, g_wts);
    cudaGetSymbolAddress((void**)&up,  g_up);
    cudaGetSymbolAddress((void**)&mid, g_mid);

    const int SMEM_S1 = (8 * 408 * 2) * 4 + 2304 * 2 * 4;                   // 44544 B
    const int SMEM_A  = (16 * 552 * 2) * 4 + 3200 * 2 * 4 + 8 * 4;          // 96288 B
    const int SMEM_B  = (8 * 408 * 2) * 4 + 4608 * 2 * 4 + 64 * 4;          // 63232 B
    cudaFuncSetAttribute(conv_s1_mma,  cudaFuncAttributeMaxDynamicSharedMemorySize, SMEM_S1);
    cudaFuncSetAttribute(conv_p2a_mma, cudaFuncAttributeMaxDynamicSharedMemorySize, SMEM_A);
    cudaFuncSetAttribute(conv_p2b_mma, cudaFuncAttributeMaxDynamicSharedMemorySize, SMEM_B);

    dim3 b16(16, 16);

    // stage 1: dual 64->32 k3 ReLU on tensor cores
    conv_s1_mma<<<dim3(2, 32, 16), 256, SMEM_S1>>>(x, p1_w1, p1_b1, t1,
                                                   gw_w1, gw_b1, gg);
    // project1 conv2 (32->16, k3, ReLU) scalar
    conv2d_kernel<32, 16, 16, 3, true><<<dim3(8, 8, 8), b16>>>(t1, p1_w2, p1_b2, xp, 128, 128);
    gw_softmax_kernel<<<512, 256>>>(gg, gw_w2, gw_b2, wts);
    upsample_kernel<<<dim3(8, 128, 8), dim3(64, 4)>>>(xp, wts, up);

    // project2 on tensor cores (tf32 x3)
    conv_p2a_mma<<<dim3(8, 128, 8), 256, SMEM_A>>>(up, p2_w1, p2_b1, mid);
    conv_p2b_mma<<<dim3(8, 128, 8), 256, SMEM_B>>>(mid, p2_w2, p2_b2, out);
}